// round 17
// baseline (speedup 1.0000x reference)
#include <cuda_runtime.h>
#include <cuda_fp16.h>
#include <cstdint>
#include <math.h>

#define Bc 4
#define Tc 1024
#define Cc 1024
#define Hc 16
#define Dc 64
#define BT (Bc*Tc)
#define SINKc 4
#define QSCALE 0.18033688011112042f   // log2(e)/8

typedef __half h16;

// ---------------- scratch ----------------
__device__ h16   g_h  [(size_t)BT*Cc];
__device__ h16   g_q  [(size_t)BT*Cc];        // (B,H,T,D), pre-scaled by QSCALE
__device__ h16   g_k  [(size_t)BT*Cc];
__device__ h16   g_vt [(size_t)BT*Cc];        // (B,H,D,T)
__device__ h16   g_y  [(size_t)BT*Cc];        // (B,T,C)
__device__ h16   g_fc [(size_t)BT*4*Cc];
__device__ float g_x2 [(size_t)BT*Cc];
__device__ float g_part[(size_t)Bc*Hc*8*Tc];
__device__ float g_lg [(size_t)Bc*Hc*Tc];     // -log2(l) per row
__device__ float g_imp[BT];
__device__ h16   g_wat [(size_t)3*Cc*Cc];     // [N][K]
__device__ h16   g_wpt [(size_t)Cc*Cc];
__device__ h16   g_wft [(size_t)4*Cc*Cc];
__device__ h16   g_wf2t[(size_t)Cc*4*Cc];

// ---------------- helpers ----------------
__device__ __forceinline__ uint32_t smem_u32(const void* p) {
    uint32_t r;
    asm("{ .reg .u64 t; cvta.to.shared.u64 t, %1; cvt.u32.u64 %0, t; }"
        : "=r"(r) : "l"(p));
    return r;
}
__device__ __forceinline__ void ldsm4(uint32_t& r0, uint32_t& r1, uint32_t& r2, uint32_t& r3, uint32_t a) {
    asm volatile("ldmatrix.sync.aligned.m8n8.x4.shared.b16 {%0,%1,%2,%3},[%4];"
        : "=r"(r0), "=r"(r1), "=r"(r2), "=r"(r3) : "r"(a));
}
__device__ __forceinline__ void mma_f16(float* c, uint32_t a0, uint32_t a1, uint32_t a2, uint32_t a3,
                                        uint32_t b0, uint32_t b1) {
    asm volatile("mma.sync.aligned.m16n8k16.row.col.f32.f16.f16.f32 "
        "{%0,%1,%2,%3},{%4,%5,%6,%7},{%8,%9},{%0,%1,%2,%3};"
        : "+f"(c[0]), "+f"(c[1]), "+f"(c[2]), "+f"(c[3])
        : "r"(a0), "r"(a1), "r"(a2), "r"(a3), "r"(b0), "r"(b1));
}
__device__ __forceinline__ uint32_t f2h2(float a, float b) {
    __half2 h = __floats2half2_rn(a, b);
    uint32_t r;
    memcpy(&r, &h, 4);
    return r;
}
__device__ __forceinline__ uint32_t ex2h2(float a, float b) {
    uint32_t u = f2h2(a, b);
    uint32_t r;
    asm("ex2.approx.f16x2 %0, %1;" : "=r"(r) : "r"(u));
    return r;
}
__device__ __forceinline__ void cp16(uint32_t s, const void* g) {
    asm volatile("cp.async.cg.shared.global [%0], [%1], 16;" :: "r"(s), "l"(g));
}
#define CP_COMMIT() asm volatile("cp.async.commit_group;")
#define CP_WAIT0()  asm volatile("cp.async.wait_group 0;" ::: "memory")
#define CP_WAIT2()  asm volatile("cp.async.wait_group 2;")

// ---------------- fused weight transpose + ln1 ----------------
__global__ void __launch_bounds__(256) trall_kernel(
    const float* __restrict__ W0, h16* __restrict__ T0,
    const float* __restrict__ W1, h16* __restrict__ T1,
    const float* __restrict__ W2, h16* __restrict__ T2,
    const float* __restrict__ W3, h16* __restrict__ T3,
    const float* __restrict__ x, const float* __restrict__ lw,
    const float* __restrict__ lb, h16* __restrict__ lout)
{
    int bidx = blockIdx.x;
    int tid = threadIdx.x;
    if (bidx >= 12288) {
        // LayerNorm(ln1) for row bidx-12288
        int row = bidx - 12288;
        const float* xr = x + (size_t)row * Cc;
        float4 v = *(const float4*)(xr + tid * 4);
        float s  = v.x + v.y + v.z + v.w;
        float s2 = v.x*v.x + v.y*v.y + v.z*v.z + v.w*v.w;
        #pragma unroll
        for (int o = 16; o; o >>= 1) {
            s  += __shfl_xor_sync(~0u, s,  o);
            s2 += __shfl_xor_sync(~0u, s2, o);
        }
        __shared__ float ws[8], ws2[8];
        int wid = tid >> 5, lid = tid & 31;
        if (lid == 0) { ws[wid] = s; ws2[wid] = s2; }
        __syncthreads();
        if (tid < 8) {
            float a = ws[tid], a2 = ws2[tid];
            #pragma unroll
            for (int o = 4; o; o >>= 1) {
                a  += __shfl_xor_sync(0xffu, a,  o);
                a2 += __shfl_xor_sync(0xffu, a2, o);
            }
            if (tid == 0) { ws[0] = a; ws2[0] = a2; }
        }
        __syncthreads();
        float mean = ws[0] * (1.0f / Cc);
        float var  = ws2[0] * (1.0f / Cc) - mean * mean;
        float inv  = rsqrtf(var + 1e-5f);
        int c = tid * 4;
        float4 wv = *(const float4*)(lw + c);
        float4 bv = *(const float4*)(lb + c);
        uint2 pk;
        pk.x = f2h2((v.x - mean) * inv * wv.x + bv.x, (v.y - mean) * inv * wv.y + bv.y);
        pk.y = f2h2((v.z - mean) * inv * wv.z + bv.z, (v.w - mean) * inv * wv.w + bv.w);
        *(uint2*)(lout + (size_t)row * Cc + c) = pk;
        return;
    }
    __shared__ float ts[32][33];
    const float* W; h16* Wt; int K, N, gx, local;
    if (bidx < 3072)      { W = W0; Wt = T0; K = 1024; N = 3072; gx = 96;  local = bidx; }
    else if (bidx < 4096) { W = W1; Wt = T1; K = 1024; N = 1024; gx = 32;  local = bidx - 3072; }
    else if (bidx < 8192) { W = W2; Wt = T2; K = 1024; N = 4096; gx = 128; local = bidx - 4096; }
    else                  { W = W3; Wt = T3; K = 4096; N = 1024; gx = 32;  local = bidx - 8192; }
    int k0 = (local / gx) * 32, n0 = (local % gx) * 32;
    int tx = tid & 31, ty = tid >> 5;
    #pragma unroll
    for (int i = 0; i < 4; i++) {
        ts[ty + i*8][tx] = W[(size_t)(k0 + ty + i*8) * N + n0 + tx];
    }
    __syncthreads();
    #pragma unroll
    for (int i = 0; i < 4; i++) {
        Wt[(size_t)(n0 + ty + i*8) * K + k0 + tx] = __float2half_rn(ts[tx][ty + i*8]);
    }
}

// ---------------- LayerNorm (fp32 in, fp16 out) ----------------
__global__ void __launch_bounds__(256) ln_kernel(const float* __restrict__ x,
                                                 const float* __restrict__ w,
                                                 const float* __restrict__ b,
                                                 h16* __restrict__ out) {
    int row = blockIdx.x;
    int tid = threadIdx.x;
    const float* xr = x + (size_t)row * Cc;
    float4 v = *(const float4*)(xr + tid * 4);
    float s  = v.x + v.y + v.z + v.w;
    float s2 = v.x*v.x + v.y*v.y + v.z*v.z + v.w*v.w;
    #pragma unroll
    for (int o = 16; o; o >>= 1) {
        s  += __shfl_xor_sync(~0u, s,  o);
        s2 += __shfl_xor_sync(~0u, s2, o);
    }
    __shared__ float ws[8], ws2[8];
    int wid = tid >> 5, lid = tid & 31;
    if (lid == 0) { ws[wid] = s; ws2[wid] = s2; }
    __syncthreads();
    if (tid < 8) {
        float a = ws[tid], a2 = ws2[tid];
        #pragma unroll
        for (int o = 4; o; o >>= 1) {
            a  += __shfl_xor_sync(0xffu, a,  o);
            a2 += __shfl_xor_sync(0xffu, a2, o);
        }
        if (tid == 0) { ws[0] = a; ws2[0] = a2; }
    }
    __syncthreads();
    float mean = ws[0] * (1.0f / Cc);
    float var  = ws2[0] * (1.0f / Cc) - mean * mean;
    float inv  = rsqrtf(var + 1e-5f);
    int c = tid * 4;
    float4 wv = *(const float4*)(w + c);
    float4 bv = *(const float4*)(b + c);
    uint2 pk;
    pk.x = f2h2((v.x - mean) * inv * wv.x + bv.x, (v.y - mean) * inv * wv.y + bv.y);
    pk.y = f2h2((v.z - mean) * inv * wv.z + bv.z, (v.w - mean) * inv * wv.w + bv.w);
    *(uint2*)(out + (size_t)row * Cc + c) = pk;
}

// ---------------- fp16 MMA GEMM 128x128x32, cp.async 4-stage, occ 2 ----------------
#define GSTAGES 4
#define GSMEM_BYTES (GSTAGES * 2 * 128 * 40 * 2)
template<int EPI>
__global__ void __launch_bounds__(256, 2) mma_gemm(
    const h16* __restrict__ A, const h16* __restrict__ Bt,
    const float* __restrict__ bias, const float* __restrict__ res,
    float* __restrict__ outF, h16* __restrict__ outQ,
    h16* __restrict__ outK, h16* __restrict__ outVt,
    h16* __restrict__ outH,
    int M, int N, int K)
{
    extern __shared__ h16 dsm[];
    typedef h16 (*Tile)[128][40];
    Tile As = (Tile)dsm;
    Tile Bs = (Tile)(dsm + (size_t)GSTAGES * 128 * 40);

    int tid = threadIdx.x, lane = tid & 31, wid = tid >> 5;
    int wm = wid & 3, wn = wid >> 2;
    int bm = blockIdx.y * 128, bn = blockIdx.x * 128;

    float acc[2][8][4];
    #pragma unroll
    for (int i = 0; i < 2; i++) {
        #pragma unroll
        for (int j = 0; j < 8; j++) {
            #pragma unroll
            for (int k = 0; k < 4; k++) { acc[i][j][k] = 0.f; }
        }
    }

    int row = tid >> 1, kc = (tid & 1) * 16;
    const h16* Ap = A  + (size_t)(bm + row) * K + kc;
    const h16* Bp = Bt + (size_t)(bn + row) * K + kc;

    #pragma unroll
    for (int s = 0; s < GSTAGES - 1; s++) {
        int k0 = s * 32;
        cp16(smem_u32(&As[s][row][kc]),     Ap + k0);
        cp16(smem_u32(&As[s][row][kc + 8]), Ap + k0 + 8);
        cp16(smem_u32(&Bs[s][row][kc]),     Bp + k0);
        cp16(smem_u32(&Bs[s][row][kc + 8]), Bp + k0 + 8);
        CP_COMMIT();
    }

    int nk = K >> 5;
    for (int it = 0; it < nk; it++) {
        CP_WAIT2();
        __syncthreads();
        int st = it & (GSTAGES - 1);
        int nx = it + GSTAGES - 1;
        if (nx < nk) {
            int sx = nx & (GSTAGES - 1);
            int k0 = nx << 5;
            cp16(smem_u32(&As[sx][row][kc]),     Ap + k0);
            cp16(smem_u32(&As[sx][row][kc + 8]), Ap + k0 + 8);
            cp16(smem_u32(&Bs[sx][row][kc]),     Bp + k0);
            cp16(smem_u32(&Bs[sx][row][kc + 8]), Bp + k0 + 8);
        }
        CP_COMMIT();
        #pragma unroll
        for (int kk = 0; kk < 32; kk += 16) {
            uint32_t af[2][4];
            #pragma unroll
            for (int mt = 0; mt < 2; mt++) {
                ldsm4(af[mt][0], af[mt][1], af[mt][2], af[mt][3],
                      smem_u32(&As[st][wm*32 + mt*16 + (lane & 15)][kk + (lane >> 4) * 8]));
            }
            uint32_t bfr[8][2];
            #pragma unroll
            for (int np = 0; np < 4; np++) {
                uint32_t r0, r1, r2, r3;
                ldsm4(r0, r1, r2, r3,
                      smem_u32(&Bs[st][wn*64 + np*16 + (lane & 15)][kk + (lane >> 4) * 8]));
                bfr[np*2][0] = r0;   bfr[np*2][1] = r2;
                bfr[np*2+1][0] = r1; bfr[np*2+1][1] = r3;
            }
            #pragma unroll
            for (int mt = 0; mt < 2; mt++) {
                #pragma unroll
                for (int nt = 0; nt < 8; nt++) {
                    mma_f16(acc[mt][nt], af[mt][0], af[mt][1], af[mt][2], af[mt][3],
                            bfr[nt][0], bfr[nt][1]);
                }
            }
        }
    }

    #pragma unroll
    for (int mt = 0; mt < 2; mt++) {
        #pragma unroll
        for (int nt = 0; nt < 8; nt++) {
            int r0 = bm + wm*32 + mt*16 + (lane >> 2);
            int c0 = bn + wn*64 + nt*8 + (lane & 3) * 2;
            float bb0 = bias[c0], bb1 = bias[c0 + 1];
            #pragma unroll
            for (int rr = 0; rr < 2; rr++) {
                int rg = r0 + rr * 8;
                float v0 = acc[mt][nt][rr*2 + 0] + bb0;
                float v1 = acc[mt][nt][rr*2 + 1] + bb1;
                if (EPI == 1) {
                    int sec = c0 >> 10, wc = c0 & 1023;
                    int h = wc >> 6, d = wc & 63;
                    int bbi = rg >> 10, t = rg & 1023;
                    if (sec == 0) {
                        *(uint32_t*)&outQ[(((size_t)(bbi*Hc + h))*Tc + t)*Dc + d] =
                            f2h2(v0 * QSCALE, v1 * QSCALE);
                    } else if (sec == 1) {
                        *(uint32_t*)&outK[(((size_t)(bbi*Hc + h))*Tc + t)*Dc + d] = f2h2(v0, v1);
                    } else {
                        size_t vb = (((size_t)(bbi*Hc + h))*Dc + d)*Tc + t;
                        outVt[vb] = __float2half_rn(v0);
                        outVt[vb + Tc] = __float2half_rn(v1);
                    }
                } else if (EPI == 2) {
                    size_t idx = (size_t)rg * N + c0;
                    float2 rv = *(const float2*)(res + idx);
                    float2 o; o.x = v0 + rv.x; o.y = v1 + rv.y;
                    *(float2*)(outF + idx) = o;
                } else {
                    float g0 = 0.5f * v0 * (1.0f + erff(v0 * 0.70710678118654752f));
                    float g1 = 0.5f * v1 * (1.0f + erff(v1 * 0.70710678118654752f));
                    *(uint32_t*)&outH[(size_t)rg * N + c0] = f2h2(g0, g1);
                }
            }
        }
    }
}

// ================ flash pass A: lg = -log2(sum 2^S)  (occ 3) ================
#define FA_SMEM_BYTES 36864    // Qs[128][72] + Ks[2][64][72]
__device__ __forceinline__ void compute_S_w(
    const h16 (*Qs)[72], const h16 (*Ks)[72],
    int wid, int lane, float acc[8][4])
{
    #pragma unroll
    for (int j = 0; j < 8; j++) {
        #pragma unroll
        for (int k = 0; k < 4; k++) { acc[j][k] = 0.f; }
    }
    #pragma unroll
    for (int kk = 0; kk < 64; kk += 16) {
        uint32_t af[4];
        ldsm4(af[0], af[1], af[2], af[3],
              smem_u32(&Qs[wid*16 + (lane & 15)][kk + (lane >> 4) * 8]));
        uint32_t bfr[8][2];
        #pragma unroll
        for (int np = 0; np < 4; np++) {
            uint32_t r0, r1, r2, r3;
            ldsm4(r0, r1, r2, r3,
                  smem_u32(&Ks[np*16 + (lane & 15)][kk + (lane >> 4) * 8]));
            bfr[np*2][0] = r0;   bfr[np*2][1] = r2;
            bfr[np*2+1][0] = r1; bfr[np*2+1][1] = r3;
        }
        #pragma unroll
        for (int nt = 0; nt < 8; nt++) {
            mma_f16(acc[nt], af[0], af[1], af[2], af[3], bfr[nt][0], bfr[nt][1]);
        }
    }
}

__global__ void __launch_bounds__(256, 3) flashA_kernel(const int* __restrict__ amask) {
    extern __shared__ char smc[];
    h16 (*Qs)[72] = (h16(*)[72])(smc);
    h16 (*Ks)[2][64][72] = (h16(*)[2][64][72])(smc + 18432);

    int bh = blockIdx.y, b = bh >> 4;
    int qblk = (int)(gridDim.x - 1 - blockIdx.x);
    int i0 = qblk << 7;
    int tid = threadIdx.x, lane = tid & 31, wid = tid >> 5;
    int rowk = tid >> 2, ck = (tid & 3) * 16;
    const h16* kbase = g_k + ((size_t)bh*Tc) * Dc;

    {
        int row = tid >> 1, c0 = (tid & 1) * 32;
        const h16* qp = g_q + ((size_t)bh*Tc + i0 + row)*Dc + c0;
        #pragma unroll
        for (int c8 = 0; c8 < 32; c8 += 8) {
            *(uint4*)&Qs[row][c0 + c8] = *(const uint4*)(qp + c8);
        }
    }

    int nj = (qblk + 1) * 2;
    float acc[8][4];
    float l0 = 0.f, l1 = 0.f;
    int ra = i0 + wid*16 + (lane >> 2);
    int rb = ra + 8;

    {
        const h16* kp = kbase + (size_t)rowk * Dc + ck;
        cp16(smem_u32(&(*Ks)[0][rowk][ck]),     kp);
        cp16(smem_u32(&(*Ks)[0][rowk][ck + 8]), kp + 8);
        CP_COMMIT();
    }
    for (int jb = 0; jb < nj; jb++) {
        int j0 = jb << 6;
        CP_WAIT0();
        __syncthreads();
        if (jb + 1 < nj) {
            const h16* kp = kbase + (size_t)(j0 + 64 + rowk) * Dc + ck;
            int bf = (jb + 1) & 1;
            cp16(smem_u32(&(*Ks)[bf][rowk][ck]),     kp);
            cp16(smem_u32(&(*Ks)[bf][rowk][ck + 8]), kp + 8);
        }
        CP_COMMIT();
        compute_S_w(Qs, (*Ks)[jb & 1], wid, lane, acc);
        float e0 = 0.f, e1 = 0.f;
        #pragma unroll
        for (int nt = 0; nt < 8; nt++) {
            int c0 = j0 + nt*8 + (lane & 3) * 2;
            int am0 = amask[b*Tc + c0], am1 = amask[b*Tc + c0 + 1];
            if (c0     <= ra && am0) { e0 += exp2f(acc[nt][0]); }
            if (c0 + 1 <= ra && am1) { e0 += exp2f(acc[nt][1]); }
            if (c0     <= rb && am0) { e1 += exp2f(acc[nt][2]); }
            if (c0 + 1 <= rb && am1) { e1 += exp2f(acc[nt][3]); }
        }
        e0 += __shfl_xor_sync(~0u, e0, 1);
        e0 += __shfl_xor_sync(~0u, e0, 2);
        e1 += __shfl_xor_sync(~0u, e1, 1);
        e1 += __shfl_xor_sync(~0u, e1, 2);
        l0 += e0;
        l1 += e1;
    }
    if ((lane & 3) == 0) {
        g_lg[(size_t)bh*Tc + ra] = (l0 > 0.f) ? -__log2f(l0) : -60000.f;
        g_lg[(size_t)bh*Tc + rb] = (l1 > 0.f) ? -__log2f(l1) : -60000.f;
    }
}

// ================ flash pass B: P = 2^(S+lg); reg colsum; O = P@V  (occ 2) ================
#define OFFB_QS 0
#define OFFB_KS 18432
#define OFFB_VS 36864
#define OFFB_WR 55296
#define FB_SMEM_BYTES 57344

__global__ void __launch_bounds__(256, 2) flashB_kernel(const int* __restrict__ amask) {
    extern __shared__ char smc[];
    h16 (*Qs)[72] = (h16(*)[72])(smc + OFFB_QS);
    h16 (*Ks)[2][64][72] = (h16(*)[2][64][72])(smc + OFFB_KS);
    h16 (*Vs)[2][64][72] = (h16(*)[2][64][72])(smc + OFFB_VS);
    float (*wred)[64] = (float(*)[64])(smc + OFFB_WR);

    int bh = blockIdx.y, b = bh >> 4, h = bh & 15;
    int qblk = (int)(gridDim.x - 1 - blockIdx.x);
    int i0 = qblk << 7;
    int tid = threadIdx.x, lane = tid & 31, wid = tid >> 5;
    int rowk = tid >> 2, ck = (tid & 3) * 16;
    const h16* kbase = g_k  + ((size_t)bh*Tc) * Dc;
    const h16* vbase = g_vt + ((size_t)bh*Dc) * Tc;

    {
        int row = tid >> 1, c0 = (tid & 1) * 32;
        const h16* qp = g_q + ((size_t)bh*Tc + i0 + row)*Dc + c0;
        #pragma unroll
        for (int c8 = 0; c8 < 32; c8 += 8) {
            *(uint4*)&Qs[row][c0 + c8] = *(const uint4*)(qp + c8);
        }
    }

    int nj = (qblk + 1) * 2;
    float acc[8][4];
    int ra = i0 + wid*16 + (lane >> 2);
    int rb = ra + 8;
    float lg0 = g_lg[(size_t)bh*Tc + ra];
    float lg1 = g_lg[(size_t)bh*Tc + rb];

    float acco[8][4];
    #pragma unroll
    for (int j = 0; j < 8; j++) {
        #pragma unroll
        for (int k = 0; k < 4; k++) { acco[j][k] = 0.f; }
    }

    {
        const h16* kp = kbase + (size_t)rowk * Dc + ck;
        cp16(smem_u32(&(*Ks)[0][rowk][ck]),     kp);
        cp16(smem_u32(&(*Ks)[0][rowk][ck + 8]), kp + 8);
        const h16* vp = vbase + (size_t)rowk * Tc + ck;
        cp16(smem_u32(&(*Vs)[0][rowk][ck]),     vp);
        cp16(smem_u32(&(*Vs)[0][rowk][ck + 8]), vp + 8);
        CP_COMMIT();
    }
    for (int jb = 0; jb < nj; jb++) {
        int j0 = jb << 6;
        CP_WAIT0();
        __syncthreads();
        if (jb + 1 < nj) {
            int bf = (jb + 1) & 1;
            const h16* kp = kbase + (size_t)(j0 + 64 + rowk) * Dc + ck;
            cp16(smem_u32(&(*Ks)[bf][rowk][ck]),     kp);
            cp16(smem_u32(&(*Ks)[bf][rowk][ck + 8]), kp + 8);
            const h16* vp = vbase + (size_t)rowk * Tc + j0 + 64 + ck;
            cp16(smem_u32(&(*Vs)[bf][rowk][ck]),     vp);
            cp16(smem_u32(&(*Vs)[bf][rowk][ck + 8]), vp + 8);
        }
        CP_COMMIT();
        compute_S_w(Qs, (*Ks)[jb & 1], wid, lane, acc);
        uint32_t pa[8], pb[8];
        #pragma unroll
        for (int nt = 0; nt < 8; nt++) {
            int cl = nt*8 + (lane & 3) * 2;
            int c0 = j0 + cl;
            int am0 = amask[b*Tc + c0], am1 = amask[b*Tc + c0 + 1];
            float a0 = (c0     <= ra && am0) ? (acc[nt][0] + lg0) : -60000.f;
            float a1 = (c0 + 1 <= ra && am1) ? (acc[nt][1] + lg0) : -60000.f;
            float b0 = (c0     <= rb && am0) ? (acc[nt][2] + lg1) : -60000.f;
            float b1 = (c0 + 1 <= rb && am1) ? (acc[nt][3] + lg1) : -60000.f;
            pa[nt] = ex2h2(a0, a1);
            pb[nt] = ex2h2(b0, b1);
            __half2 ha, hb;
            memcpy(&ha, &pa[nt], 4);
            memcpy(&hb, &pb[nt], 4);
            float cs0 = __low2float(ha)  + __low2float(hb);
            float cs1 = __high2float(ha) + __high2float(hb);
            cs0 += __shfl_xor_sync(~0u, cs0, 4);
            cs0 += __shfl_xor_sync(~0u, cs0, 8);
            cs0 += __shfl_xor_sync(~0u, cs0, 16);
            cs1 += __shfl_xor_sync(~0u, cs1, 4);
            cs1 += __shfl_xor_sync(~0u, cs1, 8);
            cs1 += __shfl_xor_sync(~0u, cs1, 16);
            if (lane < 4) {
                wred[wid][nt*8 + lane*2]     = cs0;
                wred[wid][nt*8 + lane*2 + 1] = cs1;
            }
        }
        __syncthreads();
        if (tid < 64) {
            float s = 0.f;
            #pragma unroll
            for (int w = 0; w < 8; w++) { s += wred[w][tid]; }
            g_part[((size_t)bh*8 + qblk)*Tc + j0 + tid] = s;
        }
        #pragma unroll
        for (int g = 0; g < 4; g++) {
            int kk = g * 16;
            uint32_t bfr[8][2];
            #pragma unroll
            for (int np = 0; np < 4; np++) {
                uint32_t r0, r1, r2, r3;
                ldsm4(r0, r1, r2, r3,
                      smem_u32(&(*Vs)[jb & 1][np*16 + (lane & 15)][kk + (lane >> 4) * 8]));
                bfr[np*2][0] = r0;   bfr[np*2][1] = r2;
                bfr[np*2+1][0] = r1; bfr[np*2+1][1] = r3;
            }
            #pragma unroll
            for (int nt = 0; nt < 8; nt++) {
                mma_f16(acco[nt], pa[2*g], pb[2*g], pa[2*g + 1], pb[2*g + 1],
                        bfr[nt][0], bfr[nt][1]);
            }
        }
    }

    #pragma unroll
    for (int nt = 0; nt < 8; nt++) {
        int q0 = i0 + wid*16 + (lane >> 2);
        int d0 = nt*8 + (lane & 3) * 2;
        #pragma unroll
        for (int rr = 0; rr < 2; rr++) {
            int q = q0 + rr * 8;
            *(uint32_t*)&g_y[(size_t)(b*Tc + q) * Cc + h*64 + d0] =
                f2h2(acco[nt][rr*2], acco[nt][rr*2 + 1]);
        }
    }
}

// ---------------- imp reduce (triangle-aware) ----------------
__global__ void __launch_bounds__(256) impreduce_kernel() {
    int gt = blockIdx.x * 256 + threadIdx.x;
    int b = gt >> 10, t = gt & 1023;
    int q0 = t >> 7;                 // first qblk containing column t
    float s = 0.f;
    const float* pbase = g_part + (size_t)b * 128 * Tc + t;
    for (int h = 0; h < Hc; h++) {
        const float* p = pbase + (size_t)h * 8 * Tc;
        for (int q = q0; q < 8; q++) { s += p[(size_t)q * Tc]; }
    }
    float posn = (float)(Tc - t) / (float)Tc;
    g_imp[gt] = (s / (float)Hc) / (posn + 1e-8f);
}

__global__ void __launch_bounds__(1024) finalize_kernel(const int* __restrict__ amask,
                                                        const float* __restrict__ thrp,
                                                        float* __restrict__ outp) {
    int tid = threadIdx.x;
    float m = -3.4e38f;
    for (int i = tid; i < BT; i += 1024) { m = fmaxf(m, g_imp[i]); }
    __shared__ float red[32];
    #pragma unroll
    for (int o = 16; o; o >>= 1) { m = fmaxf(m, __shfl_xor_sync(~0u, m, o)); }
    if ((tid & 31) == 0) red[tid >> 5] = m;
    __syncthreads();
    if (tid < 32) {
        float v = red[tid];
        #pragma unroll
        for (int o = 16; o; o >>= 1) { v = fmaxf(v, __shfl_xor_sync(~0u, v, o)); }
        if (tid == 0) red[0] = v;
    }
    __syncthreads();
    float maxv = red[0];
    float thr = *thrp;
    float* maskp = outp + (size_t)BT * Cc;
    float* impp  = maskp + BT;
    for (int i = tid; i < BT; i += 1024) {
        int t = i & 1023;
        float iv = g_imp[i];
        if (t < SINKc) iv = maxv + 1.0f;
        float mk = (iv >= thr) ? 1.0f : 0.0f;
        if (t < SINKc) mk = 1.0f;
        if (amask[i] == 0) mk = 0.0f;
        maskp[i] = mk;
        impp[i]  = iv;
    }
}

// ---------------- launch ----------------
extern "C" void kernel_launch(void* const* d_in, const int* in_sizes, int n_in,
                              void* d_out, int out_size) {
    (void)in_sizes; (void)n_in; (void)out_size;
    const float* x      = (const float*)d_in[0];
    const int*   amask  = (const int*)  d_in[1];
    const float* W_attn = (const float*)d_in[2];
    const float* b_attn = (const float*)d_in[3];
    const float* W_proj = (const float*)d_in[4];
    const float* b_proj = (const float*)d_in[5];
    const float* ln1_w  = (const float*)d_in[6];
    const float* ln1_b  = (const float*)d_in[7];
    const float* ln2_w  = (const float*)d_in[8];
    const float* ln2_b  = (const float*)d_in[9];
    const float* W_fc   = (const float*)d_in[10];
    const float* b_fc   = (const float*)d_in[11];
    const float* W_fc2  = (const float*)d_in[12];
    const float* b_fc2  = (const float*)d_in[13];
    const float* thr    = (const float*)d_in[14];
    float* outp = (float*)d_out;

    h16 *ph, *pq, *pk, *pvt, *py, *pfc, *pwat, *pwpt, *pwft, *pwf2t;
    float *px2;
    cudaGetSymbolAddress((void**)&ph,    g_h);
    cudaGetSymbolAddress((void**)&pq,    g_q);
    cudaGetSymbolAddress((void**)&pk,    g_k);
    cudaGetSymbolAddress((void**)&pvt,   g_vt);
    cudaGetSymbolAddress((void**)&py,    g_y);
    cudaGetSymbolAddress((void**)&pfc,   g_fc);
    cudaGetSymbolAddress((void**)&px2,   g_x2);
    cudaGetSymbolAddress((void**)&pwat,  g_wat);
    cudaGetSymbolAddress((void**)&pwpt,  g_wpt);
    cudaGetSymbolAddress((void**)&pwft,  g_wft);
    cudaGetSymbolAddress((void**)&pwf2t, g_wf2t);

    cudaFuncSetAttribute(mma_gemm<1>, cudaFuncAttributeMaxDynamicSharedMemorySize, GSMEM_BYTES);
    cudaFuncSetAttribute(mma_gemm<2>, cudaFuncAttributeMaxDynamicSharedMemorySize, GSMEM_BYTES);
    cudaFuncSetAttribute(mma_gemm<3>, cudaFuncAttributeMaxDynamicSharedMemorySize, GSMEM_BYTES);
    cudaFuncSetAttribute(flashA_kernel, cudaFuncAttributeMaxDynamicSharedMemorySize, FA_SMEM_BYTES);
    cudaFuncSetAttribute(flashB_kernel, cudaFuncAttributeMaxDynamicSharedMemorySize, FB_SMEM_BYTES);

    // weights transpose + ln1 fused (independent work, one launch)
    trall_kernel<<<16384, 256>>>(W_attn, pwat, W_proj, pwpt, W_fc, pwft, W_fc2, pwf2t,
                                 x, ln1_w, ln1_b, ph);

    mma_gemm<1><<<dim3(3*Cc/128, BT/128), 256, GSMEM_BYTES>>>(ph, pwat, b_attn, nullptr,
                                                 nullptr, pq, pk, pvt, nullptr, BT, 3*Cc, Cc);
    flashA_kernel<<<dim3(Tc/128, Bc*Hc), 256, FA_SMEM_BYTES>>>(amask);
    flashB_kernel<<<dim3(Tc/128, Bc*Hc), 256, FB_SMEM_BYTES>>>(amask);
    impreduce_kernel<<<16, 256>>>();
    mma_gemm<2><<<dim3(Cc/128, BT/128), 256, GSMEM_BYTES>>>(py, pwpt, b_proj, x,
                                               px2, nullptr, nullptr, nullptr, nullptr, BT, Cc, Cc);
    ln_kernel<<<BT, 256>>>(px2, ln2_w, ln2_b, ph);
    mma_gemm<3><<<dim3(4*Cc/128, BT/128), 256, GSMEM_BYTES>>>(ph, pwft, b_fc, nullptr,
                                                 nullptr, nullptr, nullptr, nullptr, pfc, BT, 4*Cc, Cc);
    mma_gemm<2><<<dim3(Cc/128, BT/128), 256, GSMEM_BYTES>>>(pfc, pwf2t, b_fc2, px2,
                                               outp, nullptr, nullptr, nullptr, nullptr, BT, Cc, 4*Cc);
    finalize_kernel<<<1, 1024>>>(amask, thr, outp);
}